// round 11
// baseline (speedup 1.0000x reference)
#include <cuda_runtime.h>

// VolumeRenderer: B=4, HW=65536, N=48
// inputs: rgb (B,HW,N,3) f32, sigma (B,HW,N,1) f32, z_vals (B,HW,N) f32
// output: rgb_map (B*HW,3) then depth_map (B*HW), concatenated f32.
//
// 16 lanes <-> 16 samples; warp = 2 rays per pair. Each warp loops over
// 4 pairs with a 2-register-set software pipeline: pair p+1's 15 loads
// are issued before pair p's compute, so DRAM traffic stays in flight
// continuously across the shuffle-scan chains. No smem, no barriers.

#define TOTAL_RAYS (4 * 65536)   // 262144
#define NSAMP      48
#define PAIRS_PW   4             // ray-pairs per warp
#define RAYS_PW    (2 * PAIRS_PW)            // 8 rays per warp
#define RAYS_PB    (8 * RAYS_PW)             // 64 rays per 256-thr block

#define FULLM 0xffffffffu

struct RayVals {
    float z0, z1, z2, s0, s1, s2;
    float r0, g0, b0, r1, g1, b1, r2, g2, b2;
};

__device__ __forceinline__ RayVals load_ray(
    const float* __restrict__ rgb, const float* __restrict__ sigma,
    const float* __restrict__ z_vals, int ray, int sub)
{
    const size_t zb = (size_t)ray * NSAMP;
    const size_t rb = (size_t)ray * (NSAMP * 3);
    RayVals v;
    v.z0 = z_vals[zb +  0 + sub];
    v.z1 = z_vals[zb + 16 + sub];
    v.z2 = z_vals[zb + 32 + sub];
    v.s0 = sigma [zb +  0 + sub];
    v.s1 = sigma [zb + 16 + sub];
    v.s2 = sigma [zb + 32 + sub];
    v.r0 = rgb[rb + ( 0 + sub) * 3 + 0];
    v.g0 = rgb[rb + ( 0 + sub) * 3 + 1];
    v.b0 = rgb[rb + ( 0 + sub) * 3 + 2];
    v.r1 = rgb[rb + (16 + sub) * 3 + 0];
    v.g1 = rgb[rb + (16 + sub) * 3 + 1];
    v.b1 = rgb[rb + (16 + sub) * 3 + 2];
    v.r2 = rgb[rb + (32 + sub) * 3 + 0];
    v.g2 = rgb[rb + (32 + sub) * 3 + 1];
    v.b2 = rgb[rb + (32 + sub) * 3 + 2];
    return v;
}

__device__ __forceinline__ void compute_pair(
    const RayVals& v, int ray, int sub, float* __restrict__ out)
{
    // distances (z_{i+1} - z_i; last capped at 1e10)
    float z1f = __shfl_sync(FULLM, v.z1, 0, 16);
    float z2f = __shfl_sync(FULLM, v.z2, 0, 16);
    float n0  = __shfl_down_sync(FULLM, v.z0, 1, 16);
    float n1  = __shfl_down_sync(FULLM, v.z1, 1, 16);
    float n2  = __shfl_down_sync(FULLM, v.z2, 1, 16);
    bool last = (sub == 15);
    float d0 = (last ? z1f : n0) - v.z0;
    float d1 = (last ? z2f : n1) - v.z1;
    float d2 = last ? 1e10f : (n2 - v.z2);

    // opacities
    float e0 = __expf(-v.s0 * d0);
    float e1 = __expf(-v.s1 * d1);
    float e2 = __expf(-v.s2 * d2);

    // three interleaved inclusive multiplicative scans (depth 4)
    float t0 = e0 + 1e-10f, t1 = e1 + 1e-10f, t2 = e2 + 1e-10f;
#pragma unroll
    for (int k = 1; k < 16; k <<= 1) {
        float u0 = __shfl_up_sync(FULLM, t0, k, 16);
        float u1 = __shfl_up_sync(FULLM, t1, k, 16);
        float u2 = __shfl_up_sync(FULLM, t2, k, 16);
        if (sub >= k) { t0 *= u0; t1 *= u1; t2 *= u2; }
    }

    // segment coupling
    float c1 = __shfl_sync(FULLM, t0, 15, 16);
    float c2 = c1 * __shfl_sync(FULLM, t1, 15, 16);

    // exclusive transmittance
    float x0 = __shfl_up_sync(FULLM, t0, 1, 16);
    float x1 = __shfl_up_sync(FULLM, t1, 1, 16);
    float x2 = __shfl_up_sync(FULLM, t2, 1, 16);
    bool first = (sub == 0);
    float T0 = first ? 1.0f : x0;
    float T1 = c1 * (first ? 1.0f : x1);
    float T2 = c2 * (first ? 1.0f : x2);

    float w0 = (1.0f - e0) * T0;
    float w1 = (1.0f - e1) * T1;
    float w2 = (1.0f - e2) * T2;

    float pr = fmaf(w2, v.r2, fmaf(w1, v.r1, w0 * v.r0));
    float pg = fmaf(w2, v.g2, fmaf(w1, v.g1, w0 * v.g0));
    float pb = fmaf(w2, v.b2, fmaf(w1, v.b1, w0 * v.b0));
    float pd = fmaf(w2, v.z2, fmaf(w1, v.z1, w0 * v.z0));

    // transpose-reduce across the 16-lane group (10 shuffles)
#pragma unroll
    for (int k = 1; k <= 2; k <<= 1) {
        pr += __shfl_xor_sync(FULLM, pr, k, 16);
        pg += __shfl_xor_sync(FULLM, pg, k, 16);
        pb += __shfl_xor_sync(FULLM, pb, k, 16);
        pd += __shfl_xor_sync(FULLM, pd, k, 16);
    }
    int c = sub & 3;
    float vs = (c == 0) ? pr : (c == 1) ? pg : (c == 2) ? pb : pd;
    vs += __shfl_xor_sync(FULLM, vs, 4, 16);
    vs += __shfl_xor_sync(FULLM, vs, 8, 16);

    if (sub < 3) {
        out[(size_t)ray * 3 + sub] = vs;
    } else if (sub == 3) {
        out[(size_t)TOTAL_RAYS * 3 + ray] = vs;
    }
}

__global__ __launch_bounds__(256, 4)
void volrend_kernel(const float* __restrict__ rgb,
                    const float* __restrict__ sigma,
                    const float* __restrict__ z_vals,
                    float* __restrict__ out)
{
    const int tid  = threadIdx.x;
    const int warp = tid >> 5;
    const int lane = tid & 31;
    const int sub  = lane & 15;
    const int half = lane >> 4;

    const int base = blockIdx.x * RAYS_PB + warp * RAYS_PW;

    // pipeline prologue: pair 0 loads
    RayVals cur = load_ray(rgb, sigma, z_vals, base + half, sub);

#pragma unroll
    for (int p = 0; p < PAIRS_PW; ++p) {
        RayVals nxt;
        if (p + 1 < PAIRS_PW)   // issue next pair's loads BEFORE this compute
            nxt = load_ray(rgb, sigma, z_vals, base + 2 * (p + 1) + half, sub);
        compute_pair(cur, base + 2 * p + half, sub, out);
        cur = nxt;
    }
}

extern "C" void kernel_launch(void* const* d_in, const int* in_sizes, int n_in,
                              void* d_out, int out_size)
{
    const float* rgb    = (const float*)d_in[0];
    const float* sigma  = (const float*)d_in[1];
    const float* z_vals = (const float*)d_in[2];
    float* out = (float*)d_out;

    dim3 grid(TOTAL_RAYS / RAYS_PB);   // 4096 blocks
    dim3 block(256);
    volrend_kernel<<<grid, block>>>(rgb, sigma, z_vals, out);
}

// round 13
// speedup vs baseline: 1.0572x; 1.0572x over previous
#include <cuda_runtime.h>

// VolumeRenderer: B=4, HW=65536, N=48
// inputs: rgb (B,HW,N,3) f32, sigma (B,HW,N,1) f32, z_vals (B,HW,N) f32
// output: rgb_map (B*HW,3) then depth_map (B*HW), concatenated f32.
//
// Packed mapping: lane j (j<12 of a 16-lane group) owns samples 4j..4j+3
// of one ray; warp = 2 rays. All loads are float4 (z/sigma fully coalesced,
// rgb = 3 owner-strided LDG.128 with compile-time channel decode). Scan =
// in-register prefix over 4 samples + one width-16 shuffle scan of lane
// products. ~55 MIO slots/pair vs ~86 for the scalar variant.

#define TOTAL_RAYS (4 * 65536)   // 262144
#define NSAMP      48
#define RAYS_PB    16            // 256 threads = 8 warps x 2 rays  (FIXED)

#define FULLM 0xffffffffu

__global__ __launch_bounds__(256)
void volrend_kernel(const float* __restrict__ rgb,
                    const float* __restrict__ sigma,
                    const float* __restrict__ z_vals,
                    float* __restrict__ out)
{
    const int tid  = threadIdx.x;
    const int warp = tid >> 5;
    const int lane = tid & 31;
    const int sub  = lane & 15;          // lane within 16-lane ray group
    const int half = lane >> 4;          // which ray of the pair

    const int ray  = blockIdx.x * RAYS_PB + warp * 2 + half;
    const bool act = (sub < 12);         // 12 owner lanes x 4 samples = 48

    const size_t zb = (size_t)ray * NSAMP;
    const size_t rb = (size_t)ray * (NSAMP * 3);

    // ---- float4 loads ----
    float4 z4 = make_float4(0.f, 0.f, 0.f, 0.f);
    float4 s4 = z4, ra = z4, rbv = z4, rc = z4;
    if (act) {
        z4  = *reinterpret_cast<const float4*>(z_vals + zb + 4 * sub);
        s4  = *reinterpret_cast<const float4*>(sigma  + zb + 4 * sub);
        // elements 12j..12j+11: channels are compile-time:
        // ra=(r0,g0,b0,r1) rbv=(g1,b1,r2,g2) rc=(b2,r3,g3,b3)
        ra  = *reinterpret_cast<const float4*>(rgb + rb + 12 * sub + 0);
        rbv = *reinterpret_cast<const float4*>(rgb + rb + 12 * sub + 4);
        rc  = *reinterpret_cast<const float4*>(rgb + rb + 12 * sub + 8);
    }

    // ---- distances: d_i = z_{i+1} - z_i ; sample 47 capped at 1e10 ----
    float zn = __shfl_down_sync(FULLM, z4.x, 1, 16);   // z[4j+4]
    float d0 = z4.y - z4.x;
    float d1 = z4.z - z4.y;
    float d2 = z4.w - z4.z;
    float d3 = (sub == 11) ? 1e10f : (zn - z4.w);

    // ---- opacities ----
    float e0 = __expf(-s4.x * d0);
    float e1 = __expf(-s4.y * d1);
    float e2 = __expf(-s4.z * d2);
    float e3 = __expf(-s4.w * d3);
    float t0 = e0 + 1e-10f, t1 = e1 + 1e-10f;
    float t2 = e2 + 1e-10f, t3 = e3 + 1e-10f;

    // ---- in-lane prefix products ----
    float q1 = t0;
    float q2 = t0 * t1;
    float q3 = q2 * t2;
    float P  = act ? (q3 * t3) : 1.0f;   // lane total (idle lanes neutral)

    // ---- width-16 inclusive scan of lane products (4 SHFL) ----
    float incl = P;
#pragma unroll
    for (int k = 1; k < 16; k <<= 1) {
        float u = __shfl_up_sync(FULLM, incl, k, 16);
        if (sub >= k) incl *= u;
    }
    float ex = __shfl_up_sync(FULLM, incl, 1, 16);
    float Tl = (sub == 0) ? 1.0f : ex;   // product of all earlier lanes

    // ---- per-sample transmittance and weights ----
    float T0 = Tl;
    float T1 = Tl * q1;
    float T2 = Tl * q2;
    float T3 = Tl * q3;
    float w0 = T0 * (1.0f - e0);
    float w1 = T1 * (1.0f - e1);
    float w2 = T2 * (1.0f - e2);
    float w3 = T3 * (1.0f - e3);

    // ---- accumulate (channel pattern is compile-time) ----
    float R = fmaf(w0, ra.x, fmaf(w1, ra.w, fmaf(w2, rbv.z, w3 * rc.y)));
    float G = fmaf(w0, ra.y, fmaf(w1, rbv.x, fmaf(w2, rbv.w, w3 * rc.z)));
    float B = fmaf(w0, ra.z, fmaf(w1, rbv.y, fmaf(w2, rc.x,  w3 * rc.w)));
    float D = fmaf(w0, z4.x, fmaf(w1, z4.y, fmaf(w2, z4.z,  w3 * z4.w)));
    if (!act) { R = 0.f; G = 0.f; B = 0.f; D = 0.f; }

    // ---- transpose-reduce across the 16-lane group (10 SHFL) ----
#pragma unroll
    for (int k = 1; k <= 2; k <<= 1) {
        R += __shfl_xor_sync(FULLM, R, k, 16);
        G += __shfl_xor_sync(FULLM, G, k, 16);
        B += __shfl_xor_sync(FULLM, B, k, 16);
        D += __shfl_xor_sync(FULLM, D, k, 16);
    }
    int c = sub & 3;
    float vs = (c == 0) ? R : (c == 1) ? G : (c == 2) ? B : D;
    vs += __shfl_xor_sync(FULLM, vs, 4, 16);
    vs += __shfl_xor_sync(FULLM, vs, 8, 16);

    if (sub < 3) {
        out[(size_t)ray * 3 + sub] = vs;
    } else if (sub == 3) {
        out[(size_t)TOTAL_RAYS * 3 + ray] = vs;
    }
}

extern "C" void kernel_launch(void* const* d_in, const int* in_sizes, int n_in,
                              void* d_out, int out_size)
{
    const float* rgb    = (const float*)d_in[0];
    const float* sigma  = (const float*)d_in[1];
    const float* z_vals = (const float*)d_in[2];
    float* out = (float*)d_out;

    dim3 grid(TOTAL_RAYS / RAYS_PB);   // 16384 blocks
    dim3 block(256);
    volrend_kernel<<<grid, block>>>(rgb, sigma, z_vals, out);
}

// round 14
// speedup vs baseline: 1.0596x; 1.0022x over previous
#include <cuda_runtime.h>

// VolumeRenderer: B=4, HW=65536, N=48
// inputs: rgb (B,HW,N,3) f32, sigma (B,HW,N,1) f32, z_vals (B,HW,N) f32
// output: rgb_map (B*HW,3) then depth_map (B*HW), concatenated f32.
//
// Packed mapping: lane j (j<12 of a 16-lane group) owns samples 4j..4j+3
// of one ray; warp = 2 rays per pair. Each warp handles TWO pairs with all
// 10 LDG.128 front-batched (3.8 KB in flight per wait) before either
// compute phase; __launch_bounds__(256,4) = 64-reg budget keeps pair B's
// loads hoisted. Scan = in-register prefix x4 + one width-16 shuffle scan.

#define TOTAL_RAYS (4 * 65536)   // 262144
#define NSAMP      48
#define RAYS_PB    32            // 256 threads = 8 warps x 2 pairs x 2 rays

#define FULLM 0xffffffffu

struct RayPack { float4 z4, s4, ra, rb, rc; };

__device__ __forceinline__ RayPack load_pack(
    const float* __restrict__ rgb, const float* __restrict__ sigma,
    const float* __restrict__ z_vals, int ray, int sub, bool act)
{
    RayPack v;
    v.z4 = make_float4(0.f, 0.f, 0.f, 0.f);
    v.s4 = v.ra = v.rb = v.rc = v.z4;
    if (act) {
        const size_t zb = (size_t)ray * NSAMP;
        const size_t rbase = (size_t)ray * (NSAMP * 3);
        v.z4 = *reinterpret_cast<const float4*>(z_vals + zb + 4 * sub);
        v.s4 = *reinterpret_cast<const float4*>(sigma  + zb + 4 * sub);
        // elements 12j..12j+11: ra=(r0,g0,b0,r1) rb=(g1,b1,r2,g2) rc=(b2,r3,g3,b3)
        v.ra = *reinterpret_cast<const float4*>(rgb + rbase + 12 * sub + 0);
        v.rb = *reinterpret_cast<const float4*>(rgb + rbase + 12 * sub + 4);
        v.rc = *reinterpret_cast<const float4*>(rgb + rbase + 12 * sub + 8);
    }
    return v;
}

__device__ __forceinline__ void compute_pair(
    const RayPack& v, int ray, int sub, bool act, float* __restrict__ out)
{
    // distances: d_i = z_{i+1} - z_i ; sample 47 capped at 1e10
    float zn = __shfl_down_sync(FULLM, v.z4.x, 1, 16);   // z[4j+4]
    float d0 = v.z4.y - v.z4.x;
    float d1 = v.z4.z - v.z4.y;
    float d2 = v.z4.w - v.z4.z;
    float d3 = (sub == 11) ? 1e10f : (zn - v.z4.w);

    // opacities
    float e0 = __expf(-v.s4.x * d0);
    float e1 = __expf(-v.s4.y * d1);
    float e2 = __expf(-v.s4.z * d2);
    float e3 = __expf(-v.s4.w * d3);
    float t0 = e0 + 1e-10f, t1 = e1 + 1e-10f;
    float t2 = e2 + 1e-10f, t3 = e3 + 1e-10f;

    // in-lane prefix products
    float q1 = t0;
    float q2 = t0 * t1;
    float q3 = q2 * t2;
    float P  = act ? (q3 * t3) : 1.0f;   // idle lanes neutral

    // width-16 inclusive scan of lane products (4 SHFL)
    float incl = P;
#pragma unroll
    for (int k = 1; k < 16; k <<= 1) {
        float u = __shfl_up_sync(FULLM, incl, k, 16);
        if (sub >= k) incl *= u;
    }
    float ex = __shfl_up_sync(FULLM, incl, 1, 16);
    float Tl = (sub == 0) ? 1.0f : ex;

    // weights
    float w0 = Tl * (1.0f - e0);
    float w1 = Tl * q1 * (1.0f - e1);
    float w2 = Tl * q2 * (1.0f - e2);
    float w3 = Tl * q3 * (1.0f - e3);

    // accumulate (channel pattern compile-time)
    float R = fmaf(w0, v.ra.x, fmaf(w1, v.ra.w, fmaf(w2, v.rb.z, w3 * v.rc.y)));
    float G = fmaf(w0, v.ra.y, fmaf(w1, v.rb.x, fmaf(w2, v.rb.w, w3 * v.rc.z)));
    float B = fmaf(w0, v.ra.z, fmaf(w1, v.rb.y, fmaf(w2, v.rc.x, w3 * v.rc.w)));
    float D = fmaf(w0, v.z4.x, fmaf(w1, v.z4.y, fmaf(w2, v.z4.z, w3 * v.z4.w)));
    if (!act) { R = 0.f; G = 0.f; B = 0.f; D = 0.f; }

    // transpose-reduce across the 16-lane group (10 SHFL)
#pragma unroll
    for (int k = 1; k <= 2; k <<= 1) {
        R += __shfl_xor_sync(FULLM, R, k, 16);
        G += __shfl_xor_sync(FULLM, G, k, 16);
        B += __shfl_xor_sync(FULLM, B, k, 16);
        D += __shfl_xor_sync(FULLM, D, k, 16);
    }
    int c = sub & 3;
    float vs = (c == 0) ? R : (c == 1) ? G : (c == 2) ? B : D;
    vs += __shfl_xor_sync(FULLM, vs, 4, 16);
    vs += __shfl_xor_sync(FULLM, vs, 8, 16);

    if (sub < 3) {
        out[(size_t)ray * 3 + sub] = vs;
    } else if (sub == 3) {
        out[(size_t)TOTAL_RAYS * 3 + ray] = vs;
    }
}

__global__ __launch_bounds__(256, 4)
void volrend_kernel(const float* __restrict__ rgb,
                    const float* __restrict__ sigma,
                    const float* __restrict__ z_vals,
                    float* __restrict__ out)
{
    const int tid  = threadIdx.x;
    const int warp = tid >> 5;
    const int lane = tid & 31;
    const int sub  = lane & 15;
    const int half = lane >> 4;
    const bool act = (sub < 12);

    const int base = blockIdx.x * RAYS_PB + warp * 4;
    const int rayA = base + half;
    const int rayB = base + 2 + half;

    // front-batch BOTH pairs' loads: one DRAM wait covers 2 compute phases
    RayPack va = load_pack(rgb, sigma, z_vals, rayA, sub, act);
    RayPack vb = load_pack(rgb, sigma, z_vals, rayB, sub, act);

    compute_pair(va, rayA, sub, act, out);
    compute_pair(vb, rayB, sub, act, out);
}

extern "C" void kernel_launch(void* const* d_in, const int* in_sizes, int n_in,
                              void* d_out, int out_size)
{
    const float* rgb    = (const float*)d_in[0];
    const float* sigma  = (const float*)d_in[1];
    const float* z_vals = (const float*)d_in[2];
    float* out = (float*)d_out;

    dim3 grid(TOTAL_RAYS / RAYS_PB);   // 8192 blocks
    dim3 block(256);
    volrend_kernel<<<grid, block>>>(rgb, sigma, z_vals, out);
}